// round 12
// baseline (speedup 1.0000x reference)
#include <cuda_runtime.h>
#include <cuda_bf16.h>

#define NN 10000
#define EE 100000
#define KP 528          // kpairs per M row (K=1056 = 32*32 + 32)

// ---------------- device scratch (static allocations only) ----------------
__device__ __align__(16) float g_r[NN * 64];
__device__ __align__(16) float g_h[EE * 32];          // relu(ea@w1+b1)
__device__ int g_cntdst[NN];                          // zeroed in k_gemmnode after use
__device__ int g_start[NN + 1];
__device__ int g_cursor[NN];
__device__ __align__(8) int2 g_ord2[EE];              // (edge id, src) packed
__device__ __align__(16) float g_A[64 * 64];
__device__ __align__(16) float g_B[64 * 64];
__device__ __align__(16) float g_C[64 * 64];
__device__ __align__(16) float g_dv[64];
// split-bf16 operands: A = [M | Xbar] rows per node, B = [w2-perm | b2] cols
__device__ __align__(16) unsigned g_Ahi[NN * KP];
__device__ __align__(16) unsigned g_Alo[NN * KP];
__device__ __align__(16) unsigned g_Bhi[KP * 64];
__device__ __align__(16) unsigned g_Blo[KP * 64];

__device__ __forceinline__ unsigned pack_bf16(__nv_bfloat16 a, __nv_bfloat16 b) {
    __nv_bfloat162 p = __halves2bfloat162(a, b);      // a in low 16 bits (even k)
    return *(unsigned*)&p;
}

__device__ __forceinline__ unsigned split_pair(float f0, float f1, float& l0, float& l1) {
    __nv_bfloat16 h0 = __float2bfloat16_rn(f0);
    __nv_bfloat16 h1 = __float2bfloat16_rn(f1);
    l0 = f0 - __bfloat162float(h0);
    l1 = f1 - __bfloat162float(h1);
    return pack_bf16(h0, h1);
}

__device__ __forceinline__ void mma_bf16(float* acc, const unsigned* a, unsigned b0, unsigned b1) {
    asm volatile(
        "mma.sync.aligned.m16n8k16.row.col.f32.bf16.bf16.f32 "
        "{%0,%1,%2,%3}, {%4,%5,%6,%7}, {%8,%9}, {%0,%1,%2,%3};"
        : "+f"(acc[0]), "+f"(acc[1]), "+f"(acc[2]), "+f"(acc[3])
        : "r"(a[0]), "r"(a[1]), "r"(a[2]), "r"(a[3]), "r"(b0), "r"(b1));
}

// ---------------- chain A-1: histogram of dst ----------------
__global__ void k_hist(const int* __restrict__ ei) {
    int e = blockIdx.x * 256 + threadIdx.x;
    if (e < EE) atomicAdd(&g_cntdst[ei[EE + e]], 1);
}

// ---------------- chain A-2: exclusive scan over dst counts ----------------
__global__ void k_scan() {
    __shared__ int wsum[32];
    int t = threadIdx.x;              // 1024
    int lane = t & 31, wid = t >> 5;
    const int CH = 10;
    int base = t * CH;
    int loc[CH];
    int s = 0;
#pragma unroll
    for (int k = 0; k < CH; k++) {
        int idx = base + k;
        int v = (idx < NN) ? g_cntdst[idx] : 0;   // counts still needed later
        loc[k] = s; s += v;
    }
    int inc = s;
#pragma unroll
    for (int off = 1; off < 32; off <<= 1) {
        int y = __shfl_up_sync(0xffffffffu, inc, off);
        if (lane >= off) inc += y;
    }
    if (lane == 31) wsum[wid] = inc;
    __syncthreads();
    if (wid == 0) {
        int ws = wsum[lane];
#pragma unroll
        for (int off = 1; off < 32; off <<= 1) {
            int y = __shfl_up_sync(0xffffffffu, ws, off);
            if (lane >= off) ws += y;
        }
        wsum[lane] = ws;
    }
    __syncthreads();
    int excl = inc - s + ((wid > 0) ? wsum[wid - 1] : 0);
#pragma unroll
    for (int k = 0; k < CH; k++) {
        int idx = base + k;
        if (idx < NN) {
            int st = excl + loc[k];
            g_start[idx] = st;
            g_cursor[idx] = st;
        }
    }
    if (t == 1023) g_start[NN] = wsum[31];
}

// ---------------- chain A-3: scatter (edge,src) grouped by dst ----------------
__global__ void k_scatter(const int* __restrict__ ei) {
    int e = blockIdx.x * 256 + threadIdx.x;
    if (e < EE) {
        int d = ei[EE + e];
        int pos = atomicAdd(&g_cursor[d], 1);
        g_ord2[pos] = make_int2(e, ei[e]);
    }
}

// ---------------- chain B: H-GEMM | r | prep | B-split ----------------
#define PB_H  1563
#define PB_R  (PB_H + 157)
#define PB_P  (PB_R + 16)
#define PB_S  (PB_P + 132)

__global__ void __launch_bounds__(256) k_prepB(
    const float* __restrict__ x,  const float* __restrict__ b2,
    const float* __restrict__ root, const float* __restrict__ w2,
    const float* __restrict__ ea, const float* __restrict__ w1,
    const float* __restrict__ b1,
    const float* __restrict__ tw1, const float* __restrict__ tb1,
    const float* __restrict__ tw2, const float* __restrict__ tb2,
    const float* __restrict__ tw3, const float* __restrict__ tb3,
    const float* __restrict__ pw,  const float* __restrict__ pb) {
    __shared__ __align__(16) float sbuf[6400];
    int b = blockIdx.x;
    int t = threadIdx.x;

    if (b < PB_H) {
        // ---- H GEMM: g_h[e][j] = relu(sum_d ea[e,d]*w1[d,j] + b1[j]) ----
        int base = b * 64;
        float* eas = sbuf;                       // [64*16]
        float* w1s = eas + 1024;                 // [512]
        float* b1s = w1s + 512;                  // [32]
        for (int q = t; q < 1024; q += 256) {
            int gidx = base * 16 + q;
            eas[q] = (gidx < EE * 16) ? ea[gidx] : 0.f;
        }
        for (int q = t; q < 512; q += 256) w1s[q] = w1[q];
        if (t < 32) b1s[t] = b1[t];
        __syncthreads();

        int j = t & 31;                          // per-thread output col
        int elb = (t >> 5) * 8;                  // 8 edges per thread
        float w1c[16];
#pragma unroll
        for (int d = 0; d < 16; d++) w1c[d] = w1s[d * 32 + j];
        float bj = b1s[j];
#pragma unroll
        for (int k = 0; k < 8; k++) {
            int el = elb + k;
            int e = base + el;
            float acc = bj;
#pragma unroll
            for (int d = 0; d < 16; d++)
                acc = fmaf(eas[el * 16 + d], w1c[d], acc);   // broadcast LDS
            if (e < EE) g_h[e * 32 + j] = fmaxf(acc, 0.f);
        }
    } else if (b < PB_R) {
        // ---- r GEMM only (u removed — dead since M-restructure) ----
        int nb = (b - PB_H) * 64;
        float4* Wc = (float4*)sbuf;               // [i*16 + c4] root, 512 float4
        float*  xT = sbuf + 2048;                 // [i*64 + n]
        const float4* rtf4 = (const float4*)root;
#pragma unroll
        for (int q = 0; q < 2; q++) {
            int idx = q * 256 + t;                // [0,512)
            Wc[idx] = rtf4[idx];
        }
#pragma unroll
        for (int q = 0; q < 8; q++) {
            int f = q * 256 + t;
            int n = f >> 5, i = f & 31;
            xT[i * 64 + n] = (nb + n < NN) ? x[(nb + n) * 32 + i] : 0.f;
        }
        __syncthreads();

        int ng = t >> 4, cg = t & 15;             // 16 node-groups x 16 col4
        float acc[4][4];
#pragma unroll
        for (int a = 0; a < 4; a++)
#pragma unroll
            for (int c = 0; c < 4; c++) acc[a][c] = 0.f;
#pragma unroll 8
        for (int i = 0; i < 32; i++) {
            float4 xa = *(const float4*)&xT[i * 64 + ng * 4];
            float4 wv4 = Wc[i * 16 + cg];
            float xv[4] = {xa.x, xa.y, xa.z, xa.w};
            float wv[4] = {wv4.x, wv4.y, wv4.z, wv4.w};
#pragma unroll
            for (int a = 0; a < 4; a++)
#pragma unroll
                for (int c = 0; c < 4; c++) acc[a][c] = fmaf(xv[a], wv[c], acc[a][c]);
        }
        float4* r4 = (float4*)g_r;
#pragma unroll
        for (int a = 0; a < 4; a++) {
            int n = nb + ng * 4 + a;
            if (n < NN)
                r4[n * 16 + cg] = make_float4(acc[a][0], acc[a][1], acc[a][2], acc[a][3]);
        }
    } else if (b < PB_P) {
        // ---- prep: fold TCN+proj into A,B,C,dv ----
        int q = (b - PB_R) * 256 + t;            // [0,4096)
        int c = q >> 6, p = q & 63;
        float a = 0.f, bb = 0.f, cc = 0.f;
        for (int o = 0; o < 64; o++) {
            float pw0 = __ldg(&pw[o * 64 + p]);
            float pw1 = __ldg(&pw[(64 + o) * 64 + p]);
            float pw2 = __ldg(&pw[(128 + o) * 64 + p]);
            bb = fmaf(__ldg(&tw1[o * 192 + c * 3 + 0]), pw0, bb);
            a  = fmaf(__ldg(&tw2[o * 192 + c * 3 + 0]), pw1, a);
            cc = fmaf(__ldg(&tw1[o * 192 + c * 3 + 1]), pw0, cc);
            cc = fmaf(__ldg(&tw2[o * 192 + c * 3 + 1]), pw1, cc);
            cc = fmaf(__ldg(&tw3[o * 192 + c * 3 + 1]), pw2, cc);
        }
        g_A[q] = a; g_B[q] = bb; g_C[q] = cc;
        if (b == PB_R && t < 64) {
            float d = pb[t];
            for (int o = 0; o < 64; o++) {
                d = fmaf(tb1[o], pw[o * 64 + t], d);
                d = fmaf(tb2[o], pw[(64 + o) * 64 + t], d);
                d = fmaf(tb3[o], pw[(128 + o) * 64 + t], d);
            }
            g_dv[t] = d;
        }
    } else {
        // ---- B-split ----
        int idx = (b - PB_P) * 256 + t;          // [0, 33792)
        int kp = idx >> 6, c = idx & 63;
        float f0, f1;
        if (kp < 512) {
            int k0 = 2 * kp;
            int j = k0 >> 5, i0 = k0 & 31;
            f0 = w2[j * 2048 + i0 * 64 + c];
            f1 = w2[j * 2048 + (i0 + 1) * 64 + c];
        } else {
            int ip = kp - 512;
            f0 = b2[(2 * ip) * 64 + c];
            f1 = b2[(2 * ip + 1) * 64 + c];
        }
        float l0, l1;
        unsigned hi = split_pair(f0, f1, l0, l1);
        g_Bhi[kp * 64 + c] = hi;
        g_Blo[kp * 64 + c] = pack_bf16(__float2bfloat16_rn(l0), __float2bfloat16_rn(l1));
    }
}

// ---------------- join-1: M-build — 2 warps per dst (i-halves), LDS.128 broadcast ----------------
__global__ void __launch_bounds__(256) k_msg(const float* __restrict__ x) {
    __shared__ __align__(16) float xs[8][2][32];   // per-warp double-buffered x row
    __shared__ unsigned trs[8][288];               // transpose staging, pad 9
    int t = threadIdx.x;
    int w = t >> 5, l = t & 31;
    int d = blockIdx.x * 4 + (w >> 1);             // 2500 blocks -> exactly NN
    int hf = w & 1;                                // i-half
    int beg = g_start[d], end = g_start[d + 1];

    float acc[16];
#pragma unroll
    for (int i = 0; i < 16; i++) acc[i] = 0.f;
    float xbar = 0.f;

    float h0 = 0.f, x0 = 0.f, h1 = 0.f, x1 = 0.f;
    if (beg < end) {
        int2 o = __ldg(&g_ord2[beg]);
        h0 = __ldg(&g_h[o.x * 32 + l]);
        x0 = __ldg(&x[o.y * 32 + l]);
    }
    if (beg + 1 < end) {
        int2 o = __ldg(&g_ord2[beg + 1]);
        h1 = __ldg(&g_h[o.x * 32 + l]);
        x1 = __ldg(&x[o.y * 32 + l]);
    }
    for (int p = beg; p < end; p++) {
        xs[w][p & 1][l] = x0;
        __syncwarp();                              // visibility; also anti-dep for p-2 read
        float h2 = 0.f, x2 = 0.f;
        if (p + 2 < end) {
            int2 o = __ldg(&g_ord2[p + 2]);
            h2 = __ldg(&g_h[o.x * 32 + l]);
            x2 = __ldg(&x[o.y * 32 + l]);
        }
        xbar += x0;
        const float4* xv4 = (const float4*)&xs[w][p & 1][0];
#pragma unroll
        for (int q = 0; q < 4; q++) {
            float4 f = xv4[hf * 4 + q];            // broadcast LDS.128
            acc[4 * q + 0] = fmaf(h0, f.x, acc[4 * q + 0]);
            acc[4 * q + 1] = fmaf(h0, f.y, acc[4 * q + 1]);
            acc[4 * q + 2] = fmaf(h0, f.z, acc[4 * q + 2]);
            acc[4 * q + 3] = fmaf(h0, f.w, acc[4 * q + 3]);
        }
        h0 = h1; x0 = x1; h1 = h2; x1 = x2;
    }

    // split + transpose (pad-9): acc[2ip,2ip+1] = M[j=l][i = hf*16 + 2ip(+1)]
    unsigned lobits[8];
#pragma unroll
    for (int ip = 0; ip < 8; ip++) {
        float l0, l1;
        unsigned hi = split_pair(acc[2 * ip], acc[2 * ip + 1], l0, l1);
        trs[w][l * 9 + ip] = hi;
        lobits[ip] = pack_bf16(__float2bfloat16_rn(l0), __float2bfloat16_rn(l1));
    }
    __syncwarp();
#pragma unroll
    for (int c = 0; c < 8; c++) {
        int kp = 64 * c + 16 * (l >> 3) + hf * 8 + (l & 7);
        g_Ahi[d * KP + kp] = trs[w][(4 * c + (l >> 3)) * 9 + (l & 7)];
    }
    __syncwarp();
#pragma unroll
    for (int ip = 0; ip < 8; ip++) trs[w][l * 9 + ip] = lobits[ip];
    __syncwarp();
#pragma unroll
    for (int c = 0; c < 8; c++) {
        int kp = 64 * c + 16 * (l >> 3) + hf * 8 + (l & 7);
        g_Alo[d * KP + kp] = trs[w][(4 * c + (l >> 3)) * 9 + (l & 7)];
    }

    // Xbar rows (kp 512..527) — identical in both warps; hf==0 writes
    if (hf == 0) {
        float xa = __shfl_sync(0xffffffffu, xbar, 2 * (l & 15));
        float xb = __shfl_sync(0xffffffffu, xbar, 2 * (l & 15) + 1);
        if (l < 16) {
            float l0, l1;
            unsigned hi = split_pair(xa, xb, l0, l1);
            g_Ahi[d * KP + 512 + l] = hi;
            g_Alo[d * KP + 512 + l] = pack_bf16(__float2bfloat16_rn(l0), __float2bfloat16_rn(l1));
        }
    }
}

// ---------------- join-2: fused agg-GEMM + node epilogue, 32 rows/block ----------------
__global__ void __launch_bounds__(256) k_gemmnode(
    const float* __restrict__ hprev, const float* __restrict__ bias,
    float* __restrict__ hout, float* __restrict__ hhist) {
    __shared__ __align__(16) float ubuf[6720];     // 26.9 KB union
    unsigned* ash = (unsigned*)ubuf;               // [32*20]
    unsigned* asl = ash + 640;
    unsigned* bsh = ash + 1280;                    // [64*20]
    unsigned* bsl = ash + 2560;
    int t = threadIdx.x;
    int nb = blockIdx.x * 32;                      // 313 blocks
    int w = t >> 5, l = t & 31;
    int wn = w >> 2, wc = w & 3;
    int rl0 = wn * 16 + (l >> 2);                  // local rows rl0, rl0+8
    int cq = l & 3;

    float acc[2][4];
#pragma unroll
    for (int ct = 0; ct < 2; ct++)
#pragma unroll
        for (int q = 0; q < 4; q++) acc[ct][q] = 0.f;

    for (int kt = 0; kt < 33; kt++) {
        int KB = kt * 16;
        __syncthreads();
#pragma unroll
        for (int q0 = 0; q0 < 2; q0++) {
            int q = q0 * 256 + t;                  // [0,512)
            int rr = q >> 4, kp = q & 15;
            int n = nb + rr;
            unsigned vh = 0, vl = 0;
            if (n < NN) {
                vh = g_Ahi[n * KP + KB + kp];
                vl = g_Alo[n * KP + KB + kp];
            }
            ash[rr * 20 + kp] = vh;
            asl[rr * 20 + kp] = vl;
        }
#pragma unroll
        for (int q0 = 0; q0 < 4; q0++) {
            int q = q0 * 256 + t;                  // [0,1024)
            int kp = q >> 6, c = q & 63;
            bsh[c * 20 + kp] = g_Bhi[(KB + kp) * 64 + c];
            bsl[c * 20 + kp] = g_Blo[(KB + kp) * 64 + c];
        }
        __syncthreads();

#pragma unroll
        for (int ks = 0; ks < 2; ks++) {
            int kb = ks * 8 + cq;
            unsigned ah[4], al[4];
            ah[0] = ash[rl0 * 20 + kb];       ah[1] = ash[(rl0 + 8) * 20 + kb];
            ah[2] = ash[rl0 * 20 + kb + 4];   ah[3] = ash[(rl0 + 8) * 20 + kb + 4];
            al[0] = asl[rl0 * 20 + kb];       al[1] = asl[(rl0 + 8) * 20 + kb];
            al[2] = asl[rl0 * 20 + kb + 4];   al[3] = asl[(rl0 + 8) * 20 + kb + 4];
#pragma unroll
            for (int ct = 0; ct < 2; ct++) {
                int c = wc * 16 + ct * 8 + (l >> 2);
                unsigned bh0 = bsh[c * 20 + kb], bh1 = bsh[c * 20 + kb + 4];
                unsigned bl0 = bsl[c * 20 + kb], bl1 = bsl[c * 20 + kb + 4];
                mma_bf16(acc[ct], ah, bh0, bh1);
                mma_bf16(acc[ct], ah, bl0, bl1);
                mma_bf16(acc[ct], al, bh0, bh1);
            }
        }
    }
    __syncthreads();                               // phase-1 smem dead

    float* hs0 = ubuf;                             // [64 cols][35]
    float* hs1 = ubuf + 2240;
    float* hs2 = ubuf + 4480;

    // phase 2a: hg from fragments (agg never leaves registers)
    {
        int rr0 = nb + rl0, rr1 = rr0 + 8;
        float c0 = (rr0 < NN) ? fmaxf((float)g_cntdst[rr0], 1.f) : 1.f;
        float c1 = (rr1 < NN) ? fmaxf((float)g_cntdst[rr1], 1.f) : 1.f;
#pragma unroll
        for (int ct = 0; ct < 2; ct++) {
            int col = wc * 16 + ct * 8 + 2 * cq;
#pragma unroll
            for (int bq = 0; bq < 2; bq++) {
                int cc = col + bq;
                float bi = __ldg(&bias[cc]);
                if (rr0 < NN) {
                    float hg = fmaxf(acc[ct][bq] / c0 + __ldg(&g_r[rr0 * 64 + cc]) + bi, 0.f);
                    hs2[cc * 35 + rl0] = hg;
                    hhist[rr0 * 192 + 128 + cc] = hg;
                }
                if (rr1 < NN) {
                    float hg = fmaxf(acc[ct][2 + bq] / c1 + __ldg(&g_r[rr1 * 64 + cc]) + bi, 0.f);
                    hs2[cc * 35 + rl0 + 8] = hg;
                    hhist[rr1 * 192 + 128 + cc] = hg;
                }
            }
        }
    }
    // phase 2b: hp1/hp2 copy + hhist
#pragma unroll
    for (int s = 0; s < 8; s++) {
        int q = s * 256 + t;                       // [0,2048)
        int rl = q >> 6, o = q & 63;
        int n = nb + rl;
        float hp1 = 0.f, hp2 = 0.f;
        if (n < NN) {
            hp1 = hprev[n * 192 + 64 + o];
            hp2 = hprev[n * 192 + 128 + o];
            hhist[n * 192 + o] = hp1;
            hhist[n * 192 + 64 + o] = hp2;
        }
        hs0[o * 35 + rl] = hp1;
        hs1[o * 35 + rl] = hp2;
    }
    if (t < 32 && nb + t < NN) g_cntdst[nb + t] = 0;   // restore invariant
    __syncthreads();

    // phase 3: node GEMM (32 rows x 64 cols)
    int tn = t & 7, tp = t >> 3;                   // rows tn*4.., cols tp*2..
    float2 dv = *(const float2*)&g_dv[tp * 2];
    float a2[4][2];
#pragma unroll
    for (int a = 0; a < 4; a++) { a2[a][0] = dv.x; a2[a][1] = dv.y; }

#pragma unroll 8
    for (int c = 0; c < 64; c++) {
        float h0v[4], h1v[4], h2v[4];
#pragma unroll
        for (int a = 0; a < 4; a++) {
            h0v[a] = hs0[c * 35 + tn * 4 + a];
            h1v[a] = hs1[c * 35 + tn * 4 + a];
            h2v[a] = hs2[c * 35 + tn * 4 + a];
        }
        float2 av = __ldg((const float2*)&g_A[c * 64 + tp * 2]);
        float2 bv = __ldg((const float2*)&g_B[c * 64 + tp * 2]);
        float2 cv = __ldg((const float2*)&g_C[c * 64 + tp * 2]);
#pragma unroll
        for (int a = 0; a < 4; a++) {
            a2[a][0] = fmaf(h0v[a], av.x, a2[a][0]);
            a2[a][0] = fmaf(h1v[a], bv.x, a2[a][0]);
            a2[a][0] = fmaf(h2v[a], cv.x, a2[a][0]);
            a2[a][1] = fmaf(h0v[a], av.y, a2[a][1]);
            a2[a][1] = fmaf(h1v[a], bv.y, a2[a][1]);
            a2[a][1] = fmaf(h2v[a], cv.y, a2[a][1]);
        }
    }
#pragma unroll
    for (int a = 0; a < 4; a++) {
        int n = nb + tn * 4 + a;
        if (n < NN)
            *(float2*)&hout[n * 64 + tp * 2] = make_float2(a2[a][0], a2[a][1]);
    }
}

// ---------------- launch: fork {hist->scan->scatter} || {prepB}, join, msg, gemmnode ----------------
extern "C" void kernel_launch(void* const* d_in, const int* in_sizes, int n_in,
                              void* d_out, int out_size) {
    const float* x     = (const float*)d_in[0];
    const float* ea    = (const float*)d_in[1];
    const float* hprev = (const float*)d_in[2];
    const int*   ei    = (const int*)  d_in[3];
    const float* w1    = (const float*)d_in[4];
    const float* b1    = (const float*)d_in[5];
    const float* w2    = (const float*)d_in[6];
    const float* b2    = (const float*)d_in[7];
    const float* root  = (const float*)d_in[8];
    const float* bias  = (const float*)d_in[9];
    const float* tw1   = (const float*)d_in[10];
    const float* tb1   = (const float*)d_in[11];
    const float* tw2   = (const float*)d_in[12];
    const float* tb2   = (const float*)d_in[13];
    const float* tw3   = (const float*)d_in[14];
    const float* tb3   = (const float*)d_in[15];
    const float* pw    = (const float*)d_in[16];
    const float* pb    = (const float*)d_in[17];

    float* hout  = (float*)d_out;            // [N,64]
    float* hhist = hout + NN * 64;           // [N,3,64]

    static cudaStream_t sB = nullptr;
    static cudaEvent_t evFork = nullptr, evJoin = nullptr;
    if (sB == nullptr) {
        cudaStreamCreateWithFlags(&sB, cudaStreamNonBlocking);
        cudaEventCreateWithFlags(&evFork, cudaEventDisableTiming);
        cudaEventCreateWithFlags(&evJoin, cudaEventDisableTiming);
    }

    cudaEventRecord(evFork, 0);
    cudaStreamWaitEvent(sB, evFork, 0);

    // chain A (main): dst ordering
    k_hist<<<391, 256>>>(ei);
    k_scan<<<1, 1024>>>();
    k_scatter<<<391, 256>>>(ei);

    // chain B (side): H-GEMM, r, ABC prep, B-split
    k_prepB<<<PB_S, 256, 0, sB>>>(x, b2, root, w2, ea, w1, b1,
                                  tw1, tb1, tw2, tb2, tw3, tb3, pw, pb);

    cudaEventRecord(evJoin, sB);
    cudaStreamWaitEvent(0, evJoin, 0);

    k_msg<<<2500, 256>>>(x);
    k_gemmnode<<<313, 256>>>(hprev, bias, hout, hhist);
}

// round 13
// speedup vs baseline: 1.1076x; 1.1076x over previous
#include <cuda_runtime.h>
#include <cuda_bf16.h>

#define NN 10000
#define EE 100000
#define KP 528          // kpairs per M row (K=1056 = 32*32 + 32)

// ---------------- device scratch (static allocations only) ----------------
__device__ __align__(16) float g_u[NN * 64];          // dead output of proven ur branch
__device__ __align__(16) float g_r[NN * 64];
__device__ __align__(16) float g_h[EE * 32];          // relu(ea@w1+b1)
__device__ int g_cntdst[NN];                          // zeroed in k_gemmnode after use
__device__ int g_start[NN + 1];
__device__ int g_cursor[NN];
__device__ __align__(8) int2 g_ord2[EE];              // (edge id, src) packed
__device__ __align__(16) float g_A[64 * 64];
__device__ __align__(16) float g_B[64 * 64];
__device__ __align__(16) float g_C[64 * 64];
__device__ __align__(16) float g_dv[64];
// split-bf16 operands: A = [M | Xbar] rows per node, B = [w2-perm | b2] cols
__device__ __align__(16) unsigned g_Ahi[NN * KP];
__device__ __align__(16) unsigned g_Alo[NN * KP];
__device__ __align__(16) unsigned g_Bhi[KP * 64];
__device__ __align__(16) unsigned g_Blo[KP * 64];

__device__ __forceinline__ unsigned pack_bf16(__nv_bfloat16 a, __nv_bfloat16 b) {
    __nv_bfloat162 p = __halves2bfloat162(a, b);      // a in low 16 bits (even k)
    return *(unsigned*)&p;
}

__device__ __forceinline__ unsigned split_pair(float f0, float f1, float& l0, float& l1) {
    __nv_bfloat16 h0 = __float2bfloat16_rn(f0);
    __nv_bfloat16 h1 = __float2bfloat16_rn(f1);
    l0 = f0 - __bfloat162float(h0);
    l1 = f1 - __bfloat162float(h1);
    return pack_bf16(h0, h1);
}

__device__ __forceinline__ void mma_bf16(float* acc, const unsigned* a, unsigned b0, unsigned b1) {
    asm volatile(
        "mma.sync.aligned.m16n8k16.row.col.f32.bf16.bf16.f32 "
        "{%0,%1,%2,%3}, {%4,%5,%6,%7}, {%8,%9}, {%0,%1,%2,%3};"
        : "+f"(acc[0]), "+f"(acc[1]), "+f"(acc[2]), "+f"(acc[3])
        : "r"(a[0]), "r"(a[1]), "r"(a[2]), "r"(a[3]), "r"(b0), "r"(b1));
}

// ---------------- chain A-1: histogram of dst ----------------
__global__ void k_hist(const int* __restrict__ ei) {
    int e = blockIdx.x * 256 + threadIdx.x;
    if (e < EE) atomicAdd(&g_cntdst[ei[EE + e]], 1);
}

// ---------------- chain A-2: exclusive scan over dst counts ----------------
__global__ void k_scan() {
    __shared__ int wsum[32];
    int t = threadIdx.x;              // 1024
    int lane = t & 31, wid = t >> 5;
    const int CH = 10;
    int base = t * CH;
    int loc[CH];
    int s = 0;
#pragma unroll
    for (int k = 0; k < CH; k++) {
        int idx = base + k;
        int v = (idx < NN) ? g_cntdst[idx] : 0;   // counts still needed later
        loc[k] = s; s += v;
    }
    int inc = s;
#pragma unroll
    for (int off = 1; off < 32; off <<= 1) {
        int y = __shfl_up_sync(0xffffffffu, inc, off);
        if (lane >= off) inc += y;
    }
    if (lane == 31) wsum[wid] = inc;
    __syncthreads();
    if (wid == 0) {
        int ws = wsum[lane];
#pragma unroll
        for (int off = 1; off < 32; off <<= 1) {
            int y = __shfl_up_sync(0xffffffffu, ws, off);
            if (lane >= off) ws += y;
        }
        wsum[lane] = ws;
    }
    __syncthreads();
    int excl = inc - s + ((wid > 0) ? wsum[wid - 1] : 0);
#pragma unroll
    for (int k = 0; k < CH; k++) {
        int idx = base + k;
        if (idx < NN) {
            int st = excl + loc[k];
            g_start[idx] = st;
            g_cursor[idx] = st;
        }
    }
    if (t == 1023) g_start[NN] = wsum[31];
}

// ---------------- chain A-3: scatter (edge,src) grouped by dst ----------------
__global__ void k_scatter(const int* __restrict__ ei) {
    int e = blockIdx.x * 256 + threadIdx.x;
    if (e < EE) {
        int d = ei[EE + e];
        int pos = atomicAdd(&g_cursor[d], 1);
        g_ord2[pos] = make_int2(e, ei[e]);
    }
}

// ---------------- chain B: H-GEMM | u/r | prep | B-split (R11-exact) ----------------
#define PB_H  1563
#define PB_R  (PB_H + 157)
#define PB_P  (PB_R + 16)
#define PB_S  (PB_P + 132)

__global__ void __launch_bounds__(256) k_prepB(
    const float* __restrict__ x,  const float* __restrict__ b2,
    const float* __restrict__ root, const float* __restrict__ w2,
    const float* __restrict__ ea, const float* __restrict__ w1,
    const float* __restrict__ b1,
    const float* __restrict__ tw1, const float* __restrict__ tb1,
    const float* __restrict__ tw2, const float* __restrict__ tb2,
    const float* __restrict__ tw3, const float* __restrict__ tb3,
    const float* __restrict__ pw,  const float* __restrict__ pb) {
    __shared__ __align__(16) float sbuf[6400];
    int b = blockIdx.x;
    int t = threadIdx.x;

    if (b < PB_H) {
        // ---- H GEMM: g_h[e][j] = relu(sum_d ea[e,d]*w1[d,j] + b1[j]) ----
        int base = b * 64;
        float* eas = sbuf;                       // [64*16]
        float* w1s = eas + 1024;                 // [512]
        float* b1s = w1s + 512;                  // [32]
        for (int q = t; q < 1024; q += 256) {
            int gidx = base * 16 + q;
            eas[q] = (gidx < EE * 16) ? ea[gidx] : 0.f;
        }
        for (int q = t; q < 512; q += 256) w1s[q] = w1[q];
        if (t < 32) b1s[t] = b1[t];
        __syncthreads();

        int j = t & 31;                          // per-thread output col
        int elb = (t >> 5) * 8;                  // 8 edges per thread
        float w1c[16];
#pragma unroll
        for (int d = 0; d < 16; d++) w1c[d] = w1s[d * 32 + j];
        float bj = b1s[j];
#pragma unroll
        for (int k = 0; k < 8; k++) {
            int el = elb + k;
            int e = base + el;
            float acc = bj;
#pragma unroll
            for (int d = 0; d < 16; d++)
                acc = fmaf(eas[el * 16 + d], w1c[d], acc);   // broadcast LDS
            if (e < EE) g_h[e * 32 + j] = fmaxf(acc, 0.f);
        }
    } else if (b < PB_R) {
        // ---- u/r GEMM (R11-exact; u dead but licenses the 64-reg allocation) ----
        int nb = (b - PB_H) * 64;
        float4* Wc = (float4*)sbuf;
        float*  xT = sbuf + 4096;
        const float4* b2f4 = (const float4*)b2;
        const float4* rtf4 = (const float4*)root;
#pragma unroll
        for (int q = 0; q < 4; q++) {
            int idx = q * 256 + t;
            int i = idx >> 5, c4 = idx & 31;
            Wc[idx] = (c4 < 16) ? b2f4[i * 16 + c4] : rtf4[i * 16 + (c4 - 16)];
        }
#pragma unroll
        for (int q = 0; q < 8; q++) {
            int f = q * 256 + t;
            int n = f >> 5, i = f & 31;
            xT[i * 64 + n] = (nb + n < NN) ? x[(nb + n) * 32 + i] : 0.f;
        }
        __syncthreads();

        int ng = t >> 5, cg = t & 31;
        float acc[8][4];
#pragma unroll
        for (int a = 0; a < 8; a++)
#pragma unroll
            for (int c = 0; c < 4; c++) acc[a][c] = 0.f;
#pragma unroll 8
        for (int i = 0; i < 32; i++) {
            float4 xa = *(const float4*)&xT[i * 64 + ng * 8];
            float4 xb = *(const float4*)&xT[i * 64 + ng * 8 + 4];
            float4 wv4 = Wc[i * 32 + cg];
            float xv[8] = {xa.x, xa.y, xa.z, xa.w, xb.x, xb.y, xb.z, xb.w};
            float wv[4] = {wv4.x, wv4.y, wv4.z, wv4.w};
#pragma unroll
            for (int a = 0; a < 8; a++)
#pragma unroll
                for (int c = 0; c < 4; c++) acc[a][c] = fmaf(xv[a], wv[c], acc[a][c]);
        }
        float4* u4 = (float4*)g_u;
        float4* r4 = (float4*)g_r;
#pragma unroll
        for (int a = 0; a < 8; a++) {
            int n = nb + ng * 8 + a;
            if (n < NN) {
                float4 val = make_float4(acc[a][0], acc[a][1], acc[a][2], acc[a][3]);
                if (cg < 16) u4[n * 16 + cg] = val;
                else         r4[n * 16 + (cg - 16)] = val;
            }
        }
    } else if (b < PB_P) {
        // ---- prep: fold TCN+proj into A,B,C,dv ----
        int q = (b - PB_R) * 256 + t;            // [0,4096)
        int c = q >> 6, p = q & 63;
        float a = 0.f, bb = 0.f, cc = 0.f;
        for (int o = 0; o < 64; o++) {
            float pw0 = __ldg(&pw[o * 64 + p]);
            float pw1 = __ldg(&pw[(64 + o) * 64 + p]);
            float pw2 = __ldg(&pw[(128 + o) * 64 + p]);
            bb = fmaf(__ldg(&tw1[o * 192 + c * 3 + 0]), pw0, bb);
            a  = fmaf(__ldg(&tw2[o * 192 + c * 3 + 0]), pw1, a);
            cc = fmaf(__ldg(&tw1[o * 192 + c * 3 + 1]), pw0, cc);
            cc = fmaf(__ldg(&tw2[o * 192 + c * 3 + 1]), pw1, cc);
            cc = fmaf(__ldg(&tw3[o * 192 + c * 3 + 1]), pw2, cc);
        }
        g_A[q] = a; g_B[q] = bb; g_C[q] = cc;
        if (b == PB_R && t < 64) {
            float d = pb[t];
            for (int o = 0; o < 64; o++) {
                d = fmaf(tb1[o], pw[o * 64 + t], d);
                d = fmaf(tb2[o], pw[(64 + o) * 64 + t], d);
                d = fmaf(tb3[o], pw[(128 + o) * 64 + t], d);
            }
            g_dv[t] = d;
        }
    } else {
        // ---- B-split ----
        int idx = (b - PB_P) * 256 + t;          // [0, 33792)
        int kp = idx >> 6, c = idx & 63;
        float f0, f1;
        if (kp < 512) {
            int k0 = 2 * kp;
            int j = k0 >> 5, i0 = k0 & 31;
            f0 = w2[j * 2048 + i0 * 64 + c];
            f1 = w2[j * 2048 + (i0 + 1) * 64 + c];
        } else {
            int ip = kp - 512;
            f0 = b2[(2 * ip) * 64 + c];
            f1 = b2[(2 * ip + 1) * 64 + c];
        }
        float l0, l1;
        unsigned hi = split_pair(f0, f1, l0, l1);
        g_Bhi[kp * 64 + c] = hi;
        g_Blo[kp * 64 + c] = pack_bf16(__float2bfloat16_rn(l0), __float2bfloat16_rn(l1));
    }
}

// ---------------- join-1: M-build — warp per dst (R11-exact, int2 loads) ----------------
__global__ void __launch_bounds__(256) k_msg(const float* __restrict__ x) {
    __shared__ __align__(16) float xs[8][2][32];   // per-warp double-buffered x row
    __shared__ unsigned trs[8][544];               // transpose staging, pad 17
    int t = threadIdx.x;
    int w = t >> 5, l = t & 31;
    int d = blockIdx.x * 8 + w;               // 1250 blocks -> exactly NN
    int beg = g_start[d], end = g_start[d + 1];

    float acc[32];
#pragma unroll
    for (int i = 0; i < 32; i++) acc[i] = 0.f;
    float xbar = 0.f;

    float h0 = 0.f, x0 = 0.f, h1 = 0.f, x1 = 0.f;
    if (beg < end) {
        int2 o = __ldg(&g_ord2[beg]);
        h0 = __ldg(&g_h[o.x * 32 + l]);
        x0 = __ldg(&x[o.y * 32 + l]);
    }
    if (beg + 1 < end) {
        int2 o = __ldg(&g_ord2[beg + 1]);
        h1 = __ldg(&g_h[o.x * 32 + l]);
        x1 = __ldg(&x[o.y * 32 + l]);
    }
    for (int p = beg; p < end; p++) {
        xs[w][p & 1][l] = x0;
        __syncwarp();
        float h2 = 0.f, x2 = 0.f;
        if (p + 2 < end) {
            int2 o = __ldg(&g_ord2[p + 2]);
            h2 = __ldg(&g_h[o.x * 32 + l]);
            x2 = __ldg(&x[o.y * 32 + l]);
        }
        xbar += x0;
        const float4* xv4 = (const float4*)&xs[w][p & 1][0];
#pragma unroll
        for (int q = 0; q < 8; q++) {
            float4 f = xv4[q];                 // broadcast LDS.128
            acc[4 * q + 0] = fmaf(h0, f.x, acc[4 * q + 0]);
            acc[4 * q + 1] = fmaf(h0, f.y, acc[4 * q + 1]);
            acc[4 * q + 2] = fmaf(h0, f.z, acc[4 * q + 2]);
            acc[4 * q + 3] = fmaf(h0, f.w, acc[4 * q + 3]);
        }
        h0 = h1; x0 = x1; h1 = h2; x1 = x2;
        __syncwarp();                          // protect slot reuse at p+2
    }

    // split + transpose: hi pass then lo pass (pad-17, conflict-free)
    unsigned lobits[16];
#pragma unroll
    for (int ip = 0; ip < 16; ip++) {
        float l0, l1;
        unsigned hi = split_pair(acc[2 * ip], acc[2 * ip + 1], l0, l1);
        trs[w][l * 17 + ip] = hi;
        lobits[ip] = pack_bf16(__float2bfloat16_rn(l0), __float2bfloat16_rn(l1));
    }
    __syncwarp();
#pragma unroll
    for (int c = 0; c < 16; c++) {
        int q = c * 32 + l;
        g_Ahi[d * KP + q] = trs[w][(q >> 4) * 17 + (q & 15)];
    }
    __syncwarp();
#pragma unroll
    for (int ip = 0; ip < 16; ip++) trs[w][l * 17 + ip] = lobits[ip];
    __syncwarp();
#pragma unroll
    for (int c = 0; c < 16; c++) {
        int q = c * 32 + l;
        g_Alo[d * KP + q] = trs[w][(q >> 4) * 17 + (q & 15)];
    }

    // Xbar rows (kp 512..527)
    float xa = __shfl_sync(0xffffffffu, xbar, 2 * (l & 15));
    float xb = __shfl_sync(0xffffffffu, xbar, 2 * (l & 15) + 1);
    if (l < 16) {
        float l0, l1;
        unsigned hi = split_pair(xa, xb, l0, l1);
        g_Ahi[d * KP + 512 + l] = hi;
        g_Alo[d * KP + 512 + l] = pack_bf16(__float2bfloat16_rn(l0), __float2bfloat16_rn(l1));
    }
}

// ---------------- join-2: fused agg-GEMM + node epilogue, 32 rows/block ----------------
__global__ void __launch_bounds__(256) k_gemmnode(
    const float* __restrict__ hprev, const float* __restrict__ bias,
    float* __restrict__ hout, float* __restrict__ hhist) {
    __shared__ __align__(16) float ubuf[6720];     // 26.9 KB union
    unsigned* ash = (unsigned*)ubuf;               // [32*20]
    unsigned* asl = ash + 640;
    unsigned* bsh = ash + 1280;                    // [64*20]
    unsigned* bsl = ash + 2560;
    int t = threadIdx.x;
    int nb = blockIdx.x * 32;                      // 313 blocks
    int w = t >> 5, l = t & 31;
    int wn = w >> 2, wc = w & 3;
    int rl0 = wn * 16 + (l >> 2);                  // local rows rl0, rl0+8
    int cq = l & 3;

    float acc[2][4];
#pragma unroll
    for (int ct = 0; ct < 2; ct++)
#pragma unroll
        for (int q = 0; q < 4; q++) acc[ct][q] = 0.f;

    for (int kt = 0; kt < 33; kt++) {
        int KB = kt * 16;
        __syncthreads();
#pragma unroll
        for (int q0 = 0; q0 < 2; q0++) {
            int q = q0 * 256 + t;                  // [0,512)
            int rr = q >> 4, kp = q & 15;
            int n = nb + rr;
            unsigned vh = 0, vl = 0;
            if (n < NN) {
                vh = g_Ahi[n * KP + KB + kp];
                vl = g_Alo[n * KP + KB + kp];
            }
            ash[rr * 20 + kp] = vh;
            asl[rr * 20 + kp] = vl;
        }
#pragma unroll
        for (int q0 = 0; q0 < 4; q0++) {
            int q = q0 * 256 + t;                  // [0,1024)
            int kp = q >> 6, c = q & 63;
            bsh[c * 20 + kp] = g_Bhi[(KB + kp) * 64 + c];
            bsl[c * 20 + kp] = g_Blo[(KB + kp) * 64 + c];
        }
        __syncthreads();

#pragma unroll
        for (int ks = 0; ks < 2; ks++) {
            int kb = ks * 8 + cq;
            unsigned ah[4], al[4];
            ah[0] = ash[rl0 * 20 + kb];       ah[1] = ash[(rl0 + 8) * 20 + kb];
            ah[2] = ash[rl0 * 20 + kb + 4];   ah[3] = ash[(rl0 + 8) * 20 + kb + 4];
            al[0] = asl[rl0 * 20 + kb];       al[1] = asl[(rl0 + 8) * 20 + kb];
            al[2] = asl[rl0 * 20 + kb + 4];   al[3] = asl[(rl0 + 8) * 20 + kb + 4];
#pragma unroll
            for (int ct = 0; ct < 2; ct++) {
                int c = wc * 16 + ct * 8 + (l >> 2);
                unsigned bh0 = bsh[c * 20 + kb], bh1 = bsh[c * 20 + kb + 4];
                unsigned bl0 = bsl[c * 20 + kb], bl1 = bsl[c * 20 + kb + 4];
                mma_bf16(acc[ct], ah, bh0, bh1);
                mma_bf16(acc[ct], ah, bl0, bl1);
                mma_bf16(acc[ct], al, bh0, bh1);
            }
        }
    }
    __syncthreads();                               // phase-1 smem dead

    float* hs0 = ubuf;                             // [64 cols][35]
    float* hs1 = ubuf + 2240;
    float* hs2 = ubuf + 4480;

    // phase 2a: hg from fragments (agg never leaves registers)
    {
        int rr0 = nb + rl0, rr1 = rr0 + 8;
        float c0 = (rr0 < NN) ? fmaxf((float)g_cntdst[rr0], 1.f) : 1.f;
        float c1 = (rr1 < NN) ? fmaxf((float)g_cntdst[rr1], 1.f) : 1.f;
#pragma unroll
        for (int ct = 0; ct < 2; ct++) {
            int col = wc * 16 + ct * 8 + 2 * cq;
#pragma unroll
            for (int bq = 0; bq < 2; bq++) {
                int cc = col + bq;
                float bi = __ldg(&bias[cc]);
                if (rr0 < NN) {
                    float hg = fmaxf(acc[ct][bq] / c0 + __ldg(&g_r[rr0 * 64 + cc]) + bi, 0.f);
                    hs2[cc * 35 + rl0] = hg;
                    hhist[rr0 * 192 + 128 + cc] = hg;
                }
                if (rr1 < NN) {
                    float hg = fmaxf(acc[ct][2 + bq] / c1 + __ldg(&g_r[rr1 * 64 + cc]) + bi, 0.f);
                    hs2[cc * 35 + rl0 + 8] = hg;
                    hhist[rr1 * 192 + 128 + cc] = hg;
                }
            }
        }
    }
    // phase 2b: hp1/hp2 copy + hhist
#pragma unroll
    for (int s = 0; s < 8; s++) {
        int q = s * 256 + t;                       // [0,2048)
        int rl = q >> 6, o = q & 63;
        int n = nb + rl;
        float hp1 = 0.f, hp2 = 0.f;
        if (n < NN) {
            hp1 = hprev[n * 192 + 64 + o];
            hp2 = hprev[n * 192 + 128 + o];
            hhist[n * 192 + o] = hp1;
            hhist[n * 192 + 64 + o] = hp2;
        }
        hs0[o * 35 + rl] = hp1;
        hs1[o * 35 + rl] = hp2;
    }
    if (t < 32 && nb + t < NN) g_cntdst[nb + t] = 0;   // restore invariant
    __syncthreads();

    // phase 3: node GEMM (32 rows x 64 cols)
    int tn = t & 7, tp = t >> 3;                   // rows tn*4.., cols tp*2..
    float2 dv = *(const float2*)&g_dv[tp * 2];
    float a2[4][2];
#pragma unroll
    for (int a = 0; a < 4; a++) { a2[a][0] = dv.x; a2[a][1] = dv.y; }

#pragma unroll 8
    for (int c = 0; c < 64; c++) {
        float h0v[4], h1v[4], h2v[4];
#pragma unroll
        for (int a = 0; a < 4; a++) {
            h0v[a] = hs0[c * 35 + tn * 4 + a];
            h1v[a] = hs1[c * 35 + tn * 4 + a];
            h2v[a] = hs2[c * 35 + tn * 4 + a];
        }
        float2 av = __ldg((const float2*)&g_A[c * 64 + tp * 2]);
        float2 bv = __ldg((const float2*)&g_B[c * 64 + tp * 2]);
        float2 cv = __ldg((const float2*)&g_C[c * 64 + tp * 2]);
#pragma unroll
        for (int a = 0; a < 4; a++) {
            a2[a][0] = fmaf(h0v[a], av.x, a2[a][0]);
            a2[a][0] = fmaf(h1v[a], bv.x, a2[a][0]);
            a2[a][0] = fmaf(h2v[a], cv.x, a2[a][0]);
            a2[a][1] = fmaf(h0v[a], av.y, a2[a][1]);
            a2[a][1] = fmaf(h1v[a], bv.y, a2[a][1]);
            a2[a][1] = fmaf(h2v[a], cv.y, a2[a][1]);
        }
    }
#pragma unroll
    for (int a = 0; a < 4; a++) {
        int n = nb + tn * 4 + a;
        if (n < NN)
            *(float2*)&hout[n * 64 + tp * 2] = make_float2(a2[a][0], a2[a][1]);
    }
}

// ---------------- launch: fork {hist->scan->scatter} || {prepB}, join, msg, gemmnode ----------------
extern "C" void kernel_launch(void* const* d_in, const int* in_sizes, int n_in,
                              void* d_out, int out_size) {
    const float* x     = (const float*)d_in[0];
    const float* ea    = (const float*)d_in[1];
    const float* hprev = (const float*)d_in[2];
    const int*   ei    = (const int*)  d_in[3];
    const float* w1    = (const float*)d_in[4];
    const float* b1    = (const float*)d_in[5];
    const float* w2    = (const float*)d_in[6];
    const float* b2    = (const float*)d_in[7];
    const float* root  = (const float*)d_in[8];
    const float* bias  = (const float*)d_in[9];
    const float* tw1   = (const float*)d_in[10];
    const float* tb1   = (const float*)d_in[11];
    const float* tw2   = (const float*)d_in[12];
    const float* tb2   = (const float*)d_in[13];
    const float* tw3   = (const float*)d_in[14];
    const float* tb3   = (const float*)d_in[15];
    const float* pw    = (const float*)d_in[16];
    const float* pb    = (const float*)d_in[17];

    float* hout  = (float*)d_out;            // [N,64]
    float* hhist = hout + NN * 64;           // [N,3,64]

    static cudaStream_t sB = nullptr;
    static cudaEvent_t evFork = nullptr, evJoin = nullptr;
    if (sB == nullptr) {
        cudaStreamCreateWithFlags(&sB, cudaStreamNonBlocking);
        cudaEventCreateWithFlags(&evFork, cudaEventDisableTiming);
        cudaEventCreateWithFlags(&evJoin, cudaEventDisableTiming);
    }

    cudaEventRecord(evFork, 0);
    cudaStreamWaitEvent(sB, evFork, 0);

    // chain A (main): dst ordering
    k_hist<<<391, 256>>>(ei);
    k_scan<<<1, 1024>>>();
    k_scatter<<<391, 256>>>(ei);

    // chain B (side): H-GEMM, u/r, ABC prep, B-split
    k_prepB<<<PB_S, 256, 0, sB>>>(x, b2, root, w2, ea, w1, b1,
                                  tw1, tb1, tw2, tb2, tw3, tb3, pw, pb);

    cudaEventRecord(evJoin, sB);
    cudaStreamWaitEvent(0, evJoin, 0);

    k_msg<<<1250, 256>>>(x);
    k_gemmnode<<<313, 256>>>(hprev, bias, hout, hhist);
}

// round 14
// speedup vs baseline: 1.1305x; 1.0206x over previous
#include <cuda_runtime.h>
#include <cuda_bf16.h>

#define NN 10000
#define EE 100000
#define KP 528          // kpairs per M row (K=1056 = 32*32 + 32)

// ---------------- device scratch (static allocations only) ----------------
__device__ __align__(16) float g_u[NN * 64];          // dead output of proven ur branch
__device__ __align__(16) float g_r[NN * 64];
__device__ __align__(16) float g_h[EE * 32];          // relu(ea@w1+b1)
__device__ int g_cntdst[NN];                          // zeroed in k_gemmnode after use
__device__ int g_start[NN + 1];
__device__ int g_cursor[NN];
__device__ __align__(8) int2 g_ord2[EE];              // (edge id, src) packed
__device__ __align__(16) float g_A[64 * 64];
__device__ __align__(16) float g_B[64 * 64];
__device__ __align__(16) float g_C[64 * 64];
__device__ __align__(16) float g_dv[64];
// split-bf16 operands: A = [M | Xbar] rows per node, B = [w2-perm | b2] cols
__device__ __align__(16) unsigned g_Ahi[NN * KP];
__device__ __align__(16) unsigned g_Alo[NN * KP];
__device__ __align__(16) unsigned g_Bhi[KP * 64];
__device__ __align__(16) unsigned g_Blo[KP * 64];

__device__ __forceinline__ unsigned pack_bf16(__nv_bfloat16 a, __nv_bfloat16 b) {
    __nv_bfloat162 p = __halves2bfloat162(a, b);      // a in low 16 bits (even k)
    return *(unsigned*)&p;
}

__device__ __forceinline__ unsigned split_pair(float f0, float f1, float& l0, float& l1) {
    __nv_bfloat16 h0 = __float2bfloat16_rn(f0);
    __nv_bfloat16 h1 = __float2bfloat16_rn(f1);
    l0 = f0 - __bfloat162float(h0);
    l1 = f1 - __bfloat162float(h1);
    return pack_bf16(h0, h1);
}

__device__ __forceinline__ void mma_bf16(float* acc, const unsigned* a, unsigned b0, unsigned b1) {
    asm volatile(
        "mma.sync.aligned.m16n8k16.row.col.f32.bf16.bf16.f32 "
        "{%0,%1,%2,%3}, {%4,%5,%6,%7}, {%8,%9}, {%0,%1,%2,%3};"
        : "+f"(acc[0]), "+f"(acc[1]), "+f"(acc[2]), "+f"(acc[3])
        : "r"(a[0]), "r"(a[1]), "r"(a[2]), "r"(a[3]), "r"(b0), "r"(b1));
}

// ---------------- chain A-1: histogram of dst ----------------
__global__ void k_hist(const int* __restrict__ ei) {
    int e = blockIdx.x * 256 + threadIdx.x;
    if (e < EE) atomicAdd(&g_cntdst[ei[EE + e]], 1);
}

// ---------------- chain A-2: exclusive scan over dst counts ----------------
__global__ void k_scan() {
    __shared__ int wsum[32];
    int t = threadIdx.x;              // 1024
    int lane = t & 31, wid = t >> 5;
    const int CH = 10;
    int base = t * CH;
    int loc[CH];
    int s = 0;
#pragma unroll
    for (int k = 0; k < CH; k++) {
        int idx = base + k;
        int v = (idx < NN) ? g_cntdst[idx] : 0;   // counts still needed later
        loc[k] = s; s += v;
    }
    int inc = s;
#pragma unroll
    for (int off = 1; off < 32; off <<= 1) {
        int y = __shfl_up_sync(0xffffffffu, inc, off);
        if (lane >= off) inc += y;
    }
    if (lane == 31) wsum[wid] = inc;
    __syncthreads();
    if (wid == 0) {
        int ws = wsum[lane];
#pragma unroll
        for (int off = 1; off < 32; off <<= 1) {
            int y = __shfl_up_sync(0xffffffffu, ws, off);
            if (lane >= off) ws += y;
        }
        wsum[lane] = ws;
    }
    __syncthreads();
    int excl = inc - s + ((wid > 0) ? wsum[wid - 1] : 0);
#pragma unroll
    for (int k = 0; k < CH; k++) {
        int idx = base + k;
        if (idx < NN) {
            int st = excl + loc[k];
            g_start[idx] = st;
            g_cursor[idx] = st;
        }
    }
    if (t == 1023) g_start[NN] = wsum[31];
}

// ---------------- chain A-3: scatter (edge,src) grouped by dst ----------------
__global__ void k_scatter(const int* __restrict__ ei) {
    int e = blockIdx.x * 256 + threadIdx.x;
    if (e < EE) {
        int d = ei[EE + e];
        int pos = atomicAdd(&g_cursor[d], 1);
        g_ord2[pos] = make_int2(e, ei[e]);
    }
}

// ---------------- stream B: H-GEMM only (gates k_msg) ----------------
__global__ void __launch_bounds__(256) k_H(
    const float* __restrict__ ea, const float* __restrict__ w1,
    const float* __restrict__ b1) {
    __shared__ __align__(16) float sbuf[1600];
    int b = blockIdx.x;                          // 1563 blocks
    int t = threadIdx.x;

    int base = b * 64;
    float* eas = sbuf;                           // [64*16]
    float* w1s = eas + 1024;                     // [512]
    float* b1s = w1s + 512;                      // [32]
    for (int q = t; q < 1024; q += 256) {
        int gidx = base * 16 + q;
        eas[q] = (gidx < EE * 16) ? ea[gidx] : 0.f;
    }
    for (int q = t; q < 512; q += 256) w1s[q] = w1[q];
    if (t < 32) b1s[t] = b1[t];
    __syncthreads();

    int j = t & 31;                              // per-thread output col
    int elb = (t >> 5) * 8;                      // 8 edges per thread
    float w1c[16];
#pragma unroll
    for (int d = 0; d < 16; d++) w1c[d] = w1s[d * 32 + j];
    float bj = b1s[j];
#pragma unroll
    for (int k = 0; k < 8; k++) {
        int el = elb + k;
        int e = base + el;
        float acc = bj;
#pragma unroll
        for (int d = 0; d < 16; d++)
            acc = fmaf(eas[el * 16 + d], w1c[d], acc);       // broadcast LDS
        if (e < EE) g_h[e * 32 + j] = fmaxf(acc, 0.f);
    }
}

// ---------------- stream C: u/r | prep | B-split (feeds only gemmnode) ----------------
#define PR_R  157
#define PR_P  (PR_R + 16)
#define PR_S  (PR_P + 132)

__global__ void __launch_bounds__(256) k_rest(
    const float* __restrict__ x,  const float* __restrict__ b2,
    const float* __restrict__ root, const float* __restrict__ w2,
    const float* __restrict__ tw1, const float* __restrict__ tb1,
    const float* __restrict__ tw2, const float* __restrict__ tb2,
    const float* __restrict__ tw3, const float* __restrict__ tb3,
    const float* __restrict__ pw,  const float* __restrict__ pb) {
    __shared__ __align__(16) float sbuf[6400];
    int b = blockIdx.x;
    int t = threadIdx.x;

    if (b < PR_R) {
        // ---- u/r GEMM (R11-exact body) ----
        int nb = b * 64;
        float4* Wc = (float4*)sbuf;
        float*  xT = sbuf + 4096;
        const float4* b2f4 = (const float4*)b2;
        const float4* rtf4 = (const float4*)root;
#pragma unroll
        for (int q = 0; q < 4; q++) {
            int idx = q * 256 + t;
            int i = idx >> 5, c4 = idx & 31;
            Wc[idx] = (c4 < 16) ? b2f4[i * 16 + c4] : rtf4[i * 16 + (c4 - 16)];
        }
#pragma unroll
        for (int q = 0; q < 8; q++) {
            int f = q * 256 + t;
            int n = f >> 5, i = f & 31;
            xT[i * 64 + n] = (nb + n < NN) ? x[(nb + n) * 32 + i] : 0.f;
        }
        __syncthreads();

        int ng = t >> 5, cg = t & 31;
        float acc[8][4];
#pragma unroll
        for (int a = 0; a < 8; a++)
#pragma unroll
            for (int c = 0; c < 4; c++) acc[a][c] = 0.f;
#pragma unroll 8
        for (int i = 0; i < 32; i++) {
            float4 xa = *(const float4*)&xT[i * 64 + ng * 8];
            float4 xb = *(const float4*)&xT[i * 64 + ng * 8 + 4];
            float4 wv4 = Wc[i * 32 + cg];
            float xv[8] = {xa.x, xa.y, xa.z, xa.w, xb.x, xb.y, xb.z, xb.w};
            float wv[4] = {wv4.x, wv4.y, wv4.z, wv4.w};
#pragma unroll
            for (int a = 0; a < 8; a++)
#pragma unroll
                for (int c = 0; c < 4; c++) acc[a][c] = fmaf(xv[a], wv[c], acc[a][c]);
        }
        float4* u4 = (float4*)g_u;
        float4* r4 = (float4*)g_r;
#pragma unroll
        for (int a = 0; a < 8; a++) {
            int n = nb + ng * 8 + a;
            if (n < NN) {
                float4 val = make_float4(acc[a][0], acc[a][1], acc[a][2], acc[a][3]);
                if (cg < 16) u4[n * 16 + cg] = val;
                else         r4[n * 16 + (cg - 16)] = val;
            }
        }
    } else if (b < PR_P) {
        // ---- prep: fold TCN+proj into A,B,C,dv ----
        int q = (b - PR_R) * 256 + t;            // [0,4096)
        int c = q >> 6, p = q & 63;
        float a = 0.f, bb = 0.f, cc = 0.f;
        for (int o = 0; o < 64; o++) {
            float pw0 = __ldg(&pw[o * 64 + p]);
            float pw1 = __ldg(&pw[(64 + o) * 64 + p]);
            float pw2 = __ldg(&pw[(128 + o) * 64 + p]);
            bb = fmaf(__ldg(&tw1[o * 192 + c * 3 + 0]), pw0, bb);
            a  = fmaf(__ldg(&tw2[o * 192 + c * 3 + 0]), pw1, a);
            cc = fmaf(__ldg(&tw1[o * 192 + c * 3 + 1]), pw0, cc);
            cc = fmaf(__ldg(&tw2[o * 192 + c * 3 + 1]), pw1, cc);
            cc = fmaf(__ldg(&tw3[o * 192 + c * 3 + 1]), pw2, cc);
        }
        g_A[q] = a; g_B[q] = bb; g_C[q] = cc;
        if (b == PR_R && t < 64) {
            float d = pb[t];
            for (int o = 0; o < 64; o++) {
                d = fmaf(tb1[o], pw[o * 64 + t], d);
                d = fmaf(tb2[o], pw[(64 + o) * 64 + t], d);
                d = fmaf(tb3[o], pw[(128 + o) * 64 + t], d);
            }
            g_dv[t] = d;
        }
    } else {
        // ---- B-split ----
        int idx = (b - PR_P) * 256 + t;          // [0, 33792)
        int kp = idx >> 6, c = idx & 63;
        float f0, f1;
        if (kp < 512) {
            int k0 = 2 * kp;
            int j = k0 >> 5, i0 = k0 & 31;
            f0 = w2[j * 2048 + i0 * 64 + c];
            f1 = w2[j * 2048 + (i0 + 1) * 64 + c];
        } else {
            int ip = kp - 512;
            f0 = b2[(2 * ip) * 64 + c];
            f1 = b2[(2 * ip + 1) * 64 + c];
        }
        float l0, l1;
        unsigned hi = split_pair(f0, f1, l0, l1);
        g_Bhi[kp * 64 + c] = hi;
        g_Blo[kp * 64 + c] = pack_bf16(__float2bfloat16_rn(l0), __float2bfloat16_rn(l1));
    }
}

// ---------------- join-1: M-build — warp per dst (R13-exact) ----------------
__global__ void __launch_bounds__(256) k_msg(const float* __restrict__ x) {
    __shared__ __align__(16) float xs[8][2][32];   // per-warp double-buffered x row
    __shared__ unsigned trs[8][544];               // transpose staging, pad 17
    int t = threadIdx.x;
    int w = t >> 5, l = t & 31;
    int d = blockIdx.x * 8 + w;               // 1250 blocks -> exactly NN
    int beg = g_start[d], end = g_start[d + 1];

    float acc[32];
#pragma unroll
    for (int i = 0; i < 32; i++) acc[i] = 0.f;
    float xbar = 0.f;

    float h0 = 0.f, x0 = 0.f, h1 = 0.f, x1 = 0.f;
    if (beg < end) {
        int2 o = __ldg(&g_ord2[beg]);
        h0 = __ldg(&g_h[o.x * 32 + l]);
        x0 = __ldg(&x[o.y * 32 + l]);
    }
    if (beg + 1 < end) {
        int2 o = __ldg(&g_ord2[beg + 1]);
        h1 = __ldg(&g_h[o.x * 32 + l]);
        x1 = __ldg(&x[o.y * 32 + l]);
    }
    for (int p = beg; p < end; p++) {
        xs[w][p & 1][l] = x0;
        __syncwarp();
        float h2 = 0.f, x2 = 0.f;
        if (p + 2 < end) {
            int2 o = __ldg(&g_ord2[p + 2]);
            h2 = __ldg(&g_h[o.x * 32 + l]);
            x2 = __ldg(&x[o.y * 32 + l]);
        }
        xbar += x0;
        const float4* xv4 = (const float4*)&xs[w][p & 1][0];
#pragma unroll
        for (int q = 0; q < 8; q++) {
            float4 f = xv4[q];                 // broadcast LDS.128
            acc[4 * q + 0] = fmaf(h0, f.x, acc[4 * q + 0]);
            acc[4 * q + 1] = fmaf(h0, f.y, acc[4 * q + 1]);
            acc[4 * q + 2] = fmaf(h0, f.z, acc[4 * q + 2]);
            acc[4 * q + 3] = fmaf(h0, f.w, acc[4 * q + 3]);
        }
        h0 = h1; x0 = x1; h1 = h2; x1 = x2;
        __syncwarp();                          // protect slot reuse at p+2
    }

    // split + transpose: hi pass then lo pass (pad-17, conflict-free)
    unsigned lobits[16];
#pragma unroll
    for (int ip = 0; ip < 16; ip++) {
        float l0, l1;
        unsigned hi = split_pair(acc[2 * ip], acc[2 * ip + 1], l0, l1);
        trs[w][l * 17 + ip] = hi;
        lobits[ip] = pack_bf16(__float2bfloat16_rn(l0), __float2bfloat16_rn(l1));
    }
    __syncwarp();
#pragma unroll
    for (int c = 0; c < 16; c++) {
        int q = c * 32 + l;
        g_Ahi[d * KP + q] = trs[w][(q >> 4) * 17 + (q & 15)];
    }
    __syncwarp();
#pragma unroll
    for (int ip = 0; ip < 16; ip++) trs[w][l * 17 + ip] = lobits[ip];
    __syncwarp();
#pragma unroll
    for (int c = 0; c < 16; c++) {
        int q = c * 32 + l;
        g_Alo[d * KP + q] = trs[w][(q >> 4) * 17 + (q & 15)];
    }

    // Xbar rows (kp 512..527)
    float xa = __shfl_sync(0xffffffffu, xbar, 2 * (l & 15));
    float xb = __shfl_sync(0xffffffffu, xbar, 2 * (l & 15) + 1);
    if (l < 16) {
        float l0, l1;
        unsigned hi = split_pair(xa, xb, l0, l1);
        g_Ahi[d * KP + 512 + l] = hi;
        g_Alo[d * KP + 512 + l] = pack_bf16(__float2bfloat16_rn(l0), __float2bfloat16_rn(l1));
    }
}

// ---------------- join-2: fused agg-GEMM + node epilogue (R13-exact) ----------------
__global__ void __launch_bounds__(256) k_gemmnode(
    const float* __restrict__ hprev, const float* __restrict__ bias,
    float* __restrict__ hout, float* __restrict__ hhist) {
    __shared__ __align__(16) float ubuf[6720];     // 26.9 KB union
    unsigned* ash = (unsigned*)ubuf;               // [32*20]
    unsigned* asl = ash + 640;
    unsigned* bsh = ash + 1280;                    // [64*20]
    unsigned* bsl = ash + 2560;
    int t = threadIdx.x;
    int nb = blockIdx.x * 32;                      // 313 blocks
    int w = t >> 5, l = t & 31;
    int wn = w >> 2, wc = w & 3;
    int rl0 = wn * 16 + (l >> 2);                  // local rows rl0, rl0+8
    int cq = l & 3;

    float acc[2][4];
#pragma unroll
    for (int ct = 0; ct < 2; ct++)
#pragma unroll
        for (int q = 0; q < 4; q++) acc[ct][q] = 0.f;

    for (int kt = 0; kt < 33; kt++) {
        int KB = kt * 16;
        __syncthreads();
#pragma unroll
        for (int q0 = 0; q0 < 2; q0++) {
            int q = q0 * 256 + t;                  // [0,512)
            int rr = q >> 4, kp = q & 15;
            int n = nb + rr;
            unsigned vh = 0, vl = 0;
            if (n < NN) {
                vh = g_Ahi[n * KP + KB + kp];
                vl = g_Alo[n * KP + KB + kp];
            }
            ash[rr * 20 + kp] = vh;
            asl[rr * 20 + kp] = vl;
        }
#pragma unroll
        for (int q0 = 0; q0 < 4; q0++) {
            int q = q0 * 256 + t;                  // [0,1024)
            int kp = q >> 6, c = q & 63;
            bsh[c * 20 + kp] = g_Bhi[(KB + kp) * 64 + c];
            bsl[c * 20 + kp] = g_Blo[(KB + kp) * 64 + c];
        }
        __syncthreads();

#pragma unroll
        for (int ks = 0; ks < 2; ks++) {
            int kb = ks * 8 + cq;
            unsigned ah[4], al[4];
            ah[0] = ash[rl0 * 20 + kb];       ah[1] = ash[(rl0 + 8) * 20 + kb];
            ah[2] = ash[rl0 * 20 + kb + 4];   ah[3] = ash[(rl0 + 8) * 20 + kb + 4];
            al[0] = asl[rl0 * 20 + kb];       al[1] = asl[(rl0 + 8) * 20 + kb];
            al[2] = asl[rl0 * 20 + kb + 4];   al[3] = asl[(rl0 + 8) * 20 + kb + 4];
#pragma unroll
            for (int ct = 0; ct < 2; ct++) {
                int c = wc * 16 + ct * 8 + (l >> 2);
                unsigned bh0 = bsh[c * 20 + kb], bh1 = bsh[c * 20 + kb + 4];
                unsigned bl0 = bsl[c * 20 + kb], bl1 = bsl[c * 20 + kb + 4];
                mma_bf16(acc[ct], ah, bh0, bh1);
                mma_bf16(acc[ct], ah, bl0, bl1);
                mma_bf16(acc[ct], al, bh0, bh1);
            }
        }
    }
    __syncthreads();                               // phase-1 smem dead

    float* hs0 = ubuf;                             // [64 cols][35]
    float* hs1 = ubuf + 2240;
    float* hs2 = ubuf + 4480;

    // phase 2a: hg from fragments (agg never leaves registers)
    {
        int rr0 = nb + rl0, rr1 = rr0 + 8;
        float c0 = (rr0 < NN) ? fmaxf((float)g_cntdst[rr0], 1.f) : 1.f;
        float c1 = (rr1 < NN) ? fmaxf((float)g_cntdst[rr1], 1.f) : 1.f;
#pragma unroll
        for (int ct = 0; ct < 2; ct++) {
            int col = wc * 16 + ct * 8 + 2 * cq;
#pragma unroll
            for (int bq = 0; bq < 2; bq++) {
                int cc = col + bq;
                float bi = __ldg(&bias[cc]);
                if (rr0 < NN) {
                    float hg = fmaxf(acc[ct][bq] / c0 + __ldg(&g_r[rr0 * 64 + cc]) + bi, 0.f);
                    hs2[cc * 35 + rl0] = hg;
                    hhist[rr0 * 192 + 128 + cc] = hg;
                }
                if (rr1 < NN) {
                    float hg = fmaxf(acc[ct][2 + bq] / c1 + __ldg(&g_r[rr1 * 64 + cc]) + bi, 0.f);
                    hs2[cc * 35 + rl0 + 8] = hg;
                    hhist[rr1 * 192 + 128 + cc] = hg;
                }
            }
        }
    }
    // phase 2b: hp1/hp2 copy + hhist
#pragma unroll
    for (int s = 0; s < 8; s++) {
        int q = s * 256 + t;                       // [0,2048)
        int rl = q >> 6, o = q & 63;
        int n = nb + rl;
        float hp1 = 0.f, hp2 = 0.f;
        if (n < NN) {
            hp1 = hprev[n * 192 + 64 + o];
            hp2 = hprev[n * 192 + 128 + o];
            hhist[n * 192 + o] = hp1;
            hhist[n * 192 + 64 + o] = hp2;
        }
        hs0[o * 35 + rl] = hp1;
        hs1[o * 35 + rl] = hp2;
    }
    if (t < 32 && nb + t < NN) g_cntdst[nb + t] = 0;   // restore invariant
    __syncthreads();

    // phase 3: node GEMM (32 rows x 64 cols)
    int tn = t & 7, tp = t >> 3;                   // rows tn*4.., cols tp*2..
    float2 dv = *(const float2*)&g_dv[tp * 2];
    float a2[4][2];
#pragma unroll
    for (int a = 0; a < 4; a++) { a2[a][0] = dv.x; a2[a][1] = dv.y; }

#pragma unroll 8
    for (int c = 0; c < 64; c++) {
        float h0v[4], h1v[4], h2v[4];
#pragma unroll
        for (int a = 0; a < 4; a++) {
            h0v[a] = hs0[c * 35 + tn * 4 + a];
            h1v[a] = hs1[c * 35 + tn * 4 + a];
            h2v[a] = hs2[c * 35 + tn * 4 + a];
        }
        float2 av = __ldg((const float2*)&g_A[c * 64 + tp * 2]);
        float2 bv = __ldg((const float2*)&g_B[c * 64 + tp * 2]);
        float2 cv = __ldg((const float2*)&g_C[c * 64 + tp * 2]);
#pragma unroll
        for (int a = 0; a < 4; a++) {
            a2[a][0] = fmaf(h0v[a], av.x, a2[a][0]);
            a2[a][0] = fmaf(h1v[a], bv.x, a2[a][0]);
            a2[a][0] = fmaf(h2v[a], cv.x, a2[a][0]);
            a2[a][1] = fmaf(h0v[a], av.y, a2[a][1]);
            a2[a][1] = fmaf(h1v[a], bv.y, a2[a][1]);
            a2[a][1] = fmaf(h2v[a], cv.y, a2[a][1]);
        }
    }
#pragma unroll
    for (int a = 0; a < 4; a++) {
        int n = nb + tn * 4 + a;
        if (n < NN)
            *(float2*)&hout[n * 64 + tp * 2] = make_float2(a2[a][0], a2[a][1]);
    }
}

// ---------------- launch: fork {chainA} || {k_H on sB} || {k_rest on sC} ----------------
extern "C" void kernel_launch(void* const* d_in, const int* in_sizes, int n_in,
                              void* d_out, int out_size) {
    const float* x     = (const float*)d_in[0];
    const float* ea    = (const float*)d_in[1];
    const float* hprev = (const float*)d_in[2];
    const int*   ei    = (const int*)  d_in[3];
    const float* w1    = (const float*)d_in[4];
    const float* b1    = (const float*)d_in[5];
    const float* w2    = (const float*)d_in[6];
    const float* b2    = (const float*)d_in[7];
    const float* root  = (const float*)d_in[8];
    const float* bias  = (const float*)d_in[9];
    const float* tw1   = (const float*)d_in[10];
    const float* tb1   = (const float*)d_in[11];
    const float* tw2   = (const float*)d_in[12];
    const float* tb2   = (const float*)d_in[13];
    const float* tw3   = (const float*)d_in[14];
    const float* tb3   = (const float*)d_in[15];
    const float* pw    = (const float*)d_in[16];
    const float* pb    = (const float*)d_in[17];

    float* hout  = (float*)d_out;            // [N,64]
    float* hhist = hout + NN * 64;           // [N,3,64]

    static cudaStream_t sB = nullptr, sC = nullptr;
    static cudaEvent_t evFork = nullptr, evJB = nullptr, evJC = nullptr;
    if (sB == nullptr) {
        cudaStreamCreateWithFlags(&sB, cudaStreamNonBlocking);
        cudaStreamCreateWithFlags(&sC, cudaStreamNonBlocking);
        cudaEventCreateWithFlags(&evFork, cudaEventDisableTiming);
        cudaEventCreateWithFlags(&evJB, cudaEventDisableTiming);
        cudaEventCreateWithFlags(&evJC, cudaEventDisableTiming);
    }

    cudaEventRecord(evFork, 0);
    cudaStreamWaitEvent(sB, evFork, 0);
    cudaStreamWaitEvent(sC, evFork, 0);

    // chain A (main): dst ordering            — launches 1..3
    k_hist<<<391, 256>>>(ei);
    k_scan<<<1, 1024>>>();
    k_scatter<<<391, 256>>>(ei);

    // stream B: H-GEMM (gates msg)            — launch 4 (ncu target)
    k_H<<<1563, 256, 0, sB>>>(ea, w1, b1);
    cudaEventRecord(evJB, sB);
    cudaStreamWaitEvent(0, evJB, 0);

    // main: M-build                           — launch 5
    k_msg<<<1250, 256>>>(x);

    // stream C: u/r, prep, B-split (independent of everything; overlaps msg) — launch 6
    k_rest<<<PR_S, 256, 0, sC>>>(x, b2, root, w2,
                                 tw1, tb1, tw2, tb2, tw3, tb3, pw, pb);
    cudaEventRecord(evJC, sC);
    cudaStreamWaitEvent(0, evJC, 0);

    // main: fused agg-GEMM + node epilogue    — launch 7
    k_gemmnode<<<313, 256>>>(hprev, bias, hout, hhist);
}